// round 15
// baseline (speedup 1.0000x reference)
#include <cuda_runtime.h>
#include <cuda_bf16.h>
#include <cstdint>

// ---------------- problem constants ----------------
#define B_    4
#define CH_   128
#define H_    192
#define W_    192
#define ww_   96
#define NPB   9216
#define BN    36864
#define MPB   2304
#define BM    9216
#define C2_   64
#define KD_   512

// attention smem layout (uint32 units)
#define KHO(st) ((st) * 2304)
#define KLO(st) (4608 + (st) * 2304)
#define VO(st)  (9216 + (st) * 2304)
#define PPO     13824
#define ATT_SMEM_BYTES (18432 * 4)   // 73728

// ---------------- device scratch ----------------
__device__ __align__(128) float g_theta[BN * C2_];
__device__ __align__(128) uint32_t g_phiH2[BM * 32];   // [bm][c2] packed bf16x2 hi
__device__ __align__(128) uint32_t g_phiL2[BM * 32];   // lo
__device__ __align__(128) uint32_t g_gVp[B_ * C2_ * (MPB / 2)];  // [b][c][mpair] bf16x2
__device__ __align__(128) float g_omap[BN * C2_];
// fused projection weights, packed bf16x2 pairs along k: [k2][o]
__device__ __align__(128) uint32_t g_WtpH2[256 * 128];
__device__ __align__(128) uint32_t g_WtpL2[256 * 128];
__device__ __align__(128) uint32_t g_WgH2[256 * 64];
__device__ __align__(128) uint32_t g_WgL2[256 * 64];
// fused up weight, packed bf16x2 pairs along c2: [col 512][kp 32]
__device__ __align__(128) uint32_t g_WcH2[512 * 32];
__device__ __align__(128) uint32_t g_WcL2[512 * 32];
__device__ __align__(128) float g_btp[128];
__device__ __align__(128) float g_bg2[64];

// ---------------- helpers ----------------
__device__ __forceinline__ uint32_t smem_u32(const void* p) {
    uint32_t a;
    asm("{ .reg .u64 t; cvta.to.shared.u64 t, %1; cvt.u32.u64 %0, t; }" : "=r"(a) : "l"(p));
    return a;
}
__device__ __forceinline__ float ex2f(float x) {
    float r; asm("ex2.approx.ftz.f32 %0, %1;" : "=f"(r) : "f"(x)); return r;
}
__device__ __forceinline__ void cpasync16(uint32_t d, const void* s) {
    asm volatile("cp.async.cg.shared.global [%0], [%1], 16;" :: "r"(d), "l"(s));
}
#define CP_COMMIT() asm volatile("cp.async.commit_group;" ::: "memory")
#define CP_WAIT1()  asm volatile("cp.async.wait_group 1;" ::: "memory")

__device__ __forceinline__ void mma_bf16(float* c, const uint32_t* a, const uint32_t* b) {
    asm volatile(
        "mma.sync.aligned.m16n8k16.row.col.f32.bf16.bf16.f32 "
        "{%0,%1,%2,%3},{%4,%5,%6,%7},{%8,%9},{%0,%1,%2,%3};"
        : "+f"(c[0]), "+f"(c[1]), "+f"(c[2]), "+f"(c[3])
        : "r"(a[0]), "r"(a[1]), "r"(a[2]), "r"(a[3]), "r"(b[0]), "r"(b[1]));
}
__device__ __forceinline__ void ldsm4(uint32_t& r0, uint32_t& r1, uint32_t& r2,
                                      uint32_t& r3, uint32_t addr) {
    asm volatile("ldmatrix.sync.aligned.m8n8.x4.shared.b16 {%0,%1,%2,%3}, [%4];"
                 : "=r"(r0), "=r"(r1), "=r"(r2), "=r"(r3) : "r"(addr));
}
__device__ __forceinline__ void splitbf(float x, float y, uint32_t& h, uint32_t& l) {
    __nv_bfloat162 hb = __floats2bfloat162_rn(x, y);
    float hx = __bfloat162float(__low2bfloat16(hb));
    float hy = __bfloat162float(__high2bfloat16(hb));
    __nv_bfloat162 lb = __floats2bfloat162_rn(x - hx, y - hy);
    h = *reinterpret_cast<uint32_t*>(&hb);
    l = *reinterpret_cast<uint32_t*>(&lb);
}
__device__ __forceinline__ uint32_t packbf(float x, float y) {
    __nv_bfloat162 hb = __floats2bfloat162_rn(x, y);
    return *reinterpret_cast<uint32_t*>(&hb);
}
__device__ __forceinline__ float lo_bf(uint32_t u) {
    __nv_bfloat162 v = *reinterpret_cast<__nv_bfloat162*>(&u);
    return __bfloat162float(__low2bfloat16(v));
}
__device__ __forceinline__ float hi_bf(uint32_t u) {
    __nv_bfloat162 v = *reinterpret_cast<__nv_bfloat162*>(&u);
    return __bfloat162float(__high2bfloat16(v));
}

// ---------------- single prep kernel (R12) ----------------
__global__ void __launch_bounds__(256) prep_all(const float* __restrict__ thw,
                                                const float* __restrict__ phw,
                                                const float* __restrict__ gw,
                                                const float* __restrict__ d0w,
                                                const float* __restrict__ d1w,
                                                const float* __restrict__ d0b,
                                                const float* __restrict__ d1b,
                                                const float* __restrict__ ow,
                                                const float* __restrict__ uw) {
    int bid = blockIdx.x, tid = threadIdx.x;
    if (bid < 64) {
        int j = bid * 256 + tid;
        int o = j >> 7, k4 = j & 127;
        const float* wrow = (o < 64) ? (thw + o * CH_) : (phw + (o - 64) * CH_);
        float s0 = 0.f, s1 = 0.f, s2 = 0.f, s3 = 0.f;
        #pragma unroll 4
        for (int c = 0; c < CH_; c++) {
            float w = wrow[c];
            float4 d = *(const float4*)(d0w + (size_t)c * KD_ + 4 * k4);
            s0 += w * d.x; s1 += w * d.y; s2 += w * d.z; s3 += w * d.w;
        }
        uint32_t h, l;
        splitbf(s0, s1, h, l);
        g_WtpH2[(2 * k4) * 128 + o] = h; g_WtpL2[(2 * k4) * 128 + o] = l;
        splitbf(s2, s3, h, l);
        g_WtpH2[(2 * k4 + 1) * 128 + o] = h; g_WtpL2[(2 * k4 + 1) * 128 + o] = l;
    } else if (bid < 96) {
        int j = (bid - 64) * 256 + tid;
        int o = j >> 7, k4 = j & 127;
        float s0 = 0.f, s1 = 0.f, s2 = 0.f, s3 = 0.f;
        #pragma unroll 4
        for (int c = 0; c < CH_; c++) {
            float w = gw[o * CH_ + c];
            float4 d = *(const float4*)(d1w + (size_t)c * KD_ + 4 * k4);
            s0 += w * d.x; s1 += w * d.y; s2 += w * d.z; s3 += w * d.w;
        }
        uint32_t h, l;
        splitbf(s0, s1, h, l);
        g_WgH2[(2 * k4) * 64 + o] = h; g_WgL2[(2 * k4) * 64 + o] = l;
        splitbf(s2, s3, h, l);
        g_WgH2[(2 * k4 + 1) * 64 + o] = h; g_WgL2[(2 * k4 + 1) * 64 + o] = l;
    } else if (bid < 160) {
        int j = (bid - 96) * 256 + tid;
        int col = j >> 5, kp = j & 31;
        float sa = 0.f, sb2 = 0.f;
        #pragma unroll 4
        for (int ic = 0; ic < CH_; ic++) {
            float u = uw[(size_t)ic * 512 + col];
            sa  += ow[ic * C2_ + 2 * kp] * u;
            sb2 += ow[ic * C2_ + 2 * kp + 1] * u;
        }
        uint32_t h, l;
        splitbf(sa, sb2, h, l);
        g_WcH2[col * 32 + kp] = h;
        g_WcL2[col * 32 + kp] = l;
    } else {
        int o = tid;
        if (o < 128) {
            const float* wrow = (o < 64) ? (thw + o * CH_) : (phw + (o - 64) * CH_);
            float s = 0.f;
            for (int c = 0; c < CH_; c++) s += wrow[c] * d0b[c];
            g_btp[o] = s;
        } else if (o < 192) {
            int oo = o - 128;
            float s = 0.f;
            for (int c = 0; c < CH_; c++) s += gw[oo * CH_ + c] * d1b[c];
            g_bg2[oo] = s;
        }
    }
}

// ---------------- fused projection GEMM (R12 verbatim) ----------------
template <int NCOLS>
__global__ void __launch_bounds__(256) proj_gemm_kernel(const float* __restrict__ inp,
                                                        const uint32_t* __restrict__ BH,
                                                        const uint32_t* __restrict__ BL,
                                                        const float* __restrict__ bias) {
    constexpr int BST2 = NCOLS + 8;
    constexpr int SA = 4352;
    constexpr int SB = 16 * BST2;
    constexpr int STAGE = SA + 2 * SB;
    constexpr int NJ = NCOLS / 8;
    constexpr int BOPS = 16 * (NCOLS / 4);
    constexpr int PSTG = 2 * STAGE;

    extern __shared__ float sm[];
    uint32_t sb = smem_u32(sm);
    int tid = threadIdx.x;
    int lane = tid & 31, wm = tid >> 5;
    int t4 = lane & 3, t4r = lane >> 2;

    int blk = blockIdx.x;
    int b = blk / 72, r2 = blk - b * 72;
    int ti = r2 / 3, jt = r2 - ti * 3;
    const float* inb = inp + (size_t)b * CH_ * H_ * W_;

    auto prefetch = [&](int ch, int s) {
        uint32_t offA = sb + (s * STAGE) * 4;
        #pragma unroll
        for (int t = 0; t < 4; t++) {
            int o = tid + t * 256;
            int seg = o >> 4, part = o & 15;
            int ic = seg >> 3, rr = seg & 7;
            const float* src = inb + ((size_t)(ch * 8 + ic) * H_ + 8 * ti + rr) * W_
                               + 64 * jt + part * 4;
            cpasync16(offA + (seg * 68 + part * 4) * 4, src);
        }
        uint32_t offBh = sb + (s * STAGE + SA) * 4;
        uint32_t offBl = sb + (s * STAGE + SA + SB) * 4;
        #pragma unroll
        for (int o = tid; o < BOPS; o += 256) {
            int row = o / (NCOLS / 4), part = o % (NCOLS / 4);
            cpasync16(offBh + (row * BST2 + part * 4) * 4,
                      BH + (size_t)(ch * 16 + row) * NCOLS + part * 4);
            cpasync16(offBl + (row * BST2 + part * 4) * 4,
                      BL + (size_t)(ch * 16 + row) * NCOLS + part * 4);
        }
    };

    prefetch(0, 0); CP_COMMIT();
    prefetch(1, 1); CP_COMMIT();

    float acc[NJ][4];
    #pragma unroll
    for (int j = 0; j < NJ; j++)
        #pragma unroll
        for (int e = 0; e < 4; e++) acc[j][e] = 0.f;

    int n0 = wm * 16 + t4r;
    int rr0 = n0 >> 5, jj = n0 & 31;
    int p = t4 & 1;

    for (int ch = 0; ch < 16; ch++) {
        int st = ch & 1;
        CP_WAIT1();
        __syncthreads();
        const float* As = sm + st * STAGE;
        const uint32_t* Bh = (const uint32_t*)(As + SA);
        const uint32_t* Bl = Bh + SB;

        #pragma unroll
        for (int s = 0; s < 2; s++) {
            int ica = s * 4 + (t4 >> 1);
            const float* Ap = As + (ica * 8 + 2 * rr0 + p) * 68 + 2 * jj;
            float2 x0 = *(const float2*)Ap;
            float2 x1 = *(const float2*)(Ap + 16);
            float2 x2 = *(const float2*)(Ap + 16 * 68);
            float2 x3 = *(const float2*)(Ap + 16 * 68 + 16);
            uint32_t ah[4], al[4];
            splitbf(x0.x, x0.y, ah[0], al[0]);
            splitbf(x1.x, x1.y, ah[1], al[1]);
            splitbf(x2.x, x2.y, ah[2], al[2]);
            splitbf(x3.x, x3.y, ah[3], al[3]);

            int brow = (s * 8 + t4) * BST2 + t4r;
            #pragma unroll
            for (int j = 0; j < NJ; j++) {
                uint32_t bh[2], bl2[2];
                bh[0] = Bh[brow + j * 8];
                bh[1] = Bh[brow + j * 8 + 4 * BST2];
                bl2[0] = Bl[brow + j * 8];
                bl2[1] = Bl[brow + j * 8 + 4 * BST2];
                mma_bf16(acc[j], ah, bh);
                mma_bf16(acc[j], ah, bl2);
                mma_bf16(acc[j], al, bh);
            }
        }
        __syncthreads();
        if (ch + 2 < 16) { prefetch(ch + 2, st); }
        CP_COMMIT();
    }

    float* stg = sm + PSTG;
    int ng0 = b * NPB + (4 * ti + rr0) * ww_ + 32 * jt + jj;

    #pragma unroll
    for (int j = 0; j < NJ; j++) {
        int col = j * 8 + 2 * t4;
        float b0 = bias[col], b1 = bias[col + 1];
        float2 v0 = make_float2(acc[j][0] + b0, acc[j][1] + b1);
        float2 v1 = make_float2(acc[j][2] + b0, acc[j][3] + b1);
        if (NCOLS == 128 && col < 64) {
            *(float2*)&g_theta[(size_t)ng0 * C2_ + col] = v0;
            *(float2*)&g_theta[(size_t)(ng0 + 8) * C2_ + col] = v1;
        } else {
            int c = (NCOLS == 128) ? (col - 64) : col;
            *(float2*)&stg[(rr0 * 32 + jj) * 68 + c] = v0;
            *(float2*)&stg[(rr0 * 32 + jj + 8) * 68 + c] = v1;
        }
    }
    __syncthreads();

    if (NCOLS == 128) {
        #pragma unroll
        for (int t = 0; t < 4; t++) {
            int idx = tid + t * 256;
            int c2 = idx & 31, pj = (idx >> 5) & 15, pr = idx >> 9;
            const float* s00 = stg + ((2 * pr) * 32 + 2 * pj) * 68 + 2 * c2;
            float2 a0 = *(const float2*)s00;
            float2 a1 = *(const float2*)(s00 + 68);
            float2 a2 = *(const float2*)(s00 + 32 * 68);
            float2 a3 = *(const float2*)(s00 + 32 * 68 + 68);
            float vx = fmaxf(fmaxf(a0.x, a1.x), fmaxf(a2.x, a3.x));
            float vy = fmaxf(fmaxf(a0.y, a1.y), fmaxf(a2.y, a3.y));
            uint32_t h, l;
            splitbf(vx, vy, h, l);
            int mm = b * MPB + (2 * ti + pr) * 48 + 16 * jt + pj;
            g_phiH2[(size_t)mm * 32 + c2] = h;
            g_phiL2[(size_t)mm * 32 + c2] = l;
        }
    } else {
        #pragma unroll
        for (int t = 0; t < 4; t++) {
            int idx = tid + t * 256;
            int c = idx & 63, pjp = (idx >> 6) & 7, pr = idx >> 9;
            const float* s00 = stg + ((2 * pr) * 32 + 4 * pjp) * 68 + c;
            float v0 = fmaxf(fmaxf(s00[0], s00[68]),
                             fmaxf(s00[32 * 68], s00[32 * 68 + 68]));
            const float* s01 = s00 + 2 * 68;
            float v1 = fmaxf(fmaxf(s01[0], s01[68]),
                             fmaxf(s01[32 * 68], s01[32 * 68 + 68]));
            int mp = (2 * ti + pr) * 24 + 8 * jt + pjp;
            g_gVp[((size_t)b * C2_ + c) * (MPB / 2) + mp] = packbf(v0, v1);
        }
    }
}

// ---------------- flash attention (R12 verbatim) ----------------
__device__ __forceinline__ void attn_prefetch(uint32_t sb, int s, int b, int t) {
    int tid = threadIdx.x;
    int m0 = t * 64;
    #pragma unroll
    for (int i = 0; i < 2; i++) {
        int id = tid + i * 256;
        int row = id >> 3, seg = id & 7;
        cpasync16(sb + (KHO(s) + row * 36 + seg * 4) * 4,
                  g_phiH2 + (size_t)(b * MPB + m0 + row) * 32 + seg * 4);
        cpasync16(sb + (KLO(s) + row * 36 + seg * 4) * 4,
                  g_phiL2 + (size_t)(b * MPB + m0 + row) * 32 + seg * 4);
        cpasync16(sb + (VO(s) + row * 36 + seg * 4) * 4,
                  g_gVp + ((size_t)b * C2_ + row) * (MPB / 2) + m0 / 2 + seg * 4);
    }
}

__global__ void __launch_bounds__(256) attn_mma_kernel() {
    extern __shared__ float sm[];
    uint32_t sb = smem_u32(sm);
    int tid = threadIdx.x;
    int lane = tid & 31, w = tid >> 5;
    int bb = blockIdx.x / 72, qt = blockIdx.x - bb * 72;
    int qbase = bb * NPB + qt * 128;
    int t4 = lane & 3, t4r = lane >> 2;
    int q0 = 16 * w + t4r;
    int lrow = lane & 7, lg = lane >> 3;

    uint32_t lkb = (lrow * 36 + (lg >> 1) * 8 + (lg & 1) * 4) * 4;
    uint32_t lpb = ((16 * w + (lg & 1) * 8 + lrow) * 36 + (lg >> 1) * 4) * 4;
    uint32_t lvb = (((lg >> 1) * 8 + lrow) * 36 + (lg & 1) * 4) * 4;

    uint32_t qh[4][4], ql[4][4];
    {
        const float* Qg = g_theta + (size_t)qbase * C2_;
        #pragma unroll
        for (int s = 0; s < 4; s++) {
            int col = s * 16 + 2 * t4;
            float2 v00 = *(const float2*)&Qg[(size_t)q0 * C2_ + col];
            float2 v10 = *(const float2*)&Qg[(size_t)(q0 + 8) * C2_ + col];
            float2 v01 = *(const float2*)&Qg[(size_t)q0 * C2_ + col + 8];
            float2 v11 = *(const float2*)&Qg[(size_t)(q0 + 8) * C2_ + col + 8];
            splitbf(v00.x, v00.y, qh[s][0], ql[s][0]);
            splitbf(v10.x, v10.y, qh[s][1], ql[s][1]);
            splitbf(v01.x, v01.y, qh[s][2], ql[s][2]);
            splitbf(v11.x, v11.y, qh[s][3], ql[s][3]);
        }
    }

    attn_prefetch(sb, 0, bb, 0); CP_COMMIT();
    attn_prefetch(sb, 1, bb, 1); CP_COMMIT();

    float accO[8][4];
    #pragma unroll
    for (int j = 0; j < 8; j++)
        #pragma unroll
        for (int e = 0; e < 4; e++) accO[j][e] = 0.f;
    float l0 = 0.f, l1 = 0.f;

    uint32_t* Pp = (uint32_t*)sm + PPO;
    uint32_t aP = sb + PPO * 4;

    for (int t = 0; t < 36; t++) {
        int st = t & 1;
        CP_WAIT1();
        __syncthreads();
        uint32_t aKH = sb + KHO(st) * 4;
        uint32_t aKL = sb + KLO(st) * 4;
        uint32_t aV  = sb + VO(st) * 4;

        #pragma unroll
        for (int jp = 0; jp < 4; jp++) {
            int ja = jp, jb = jp + 4;
            float ca[4] = {0.f, 0.f, 0.f, 0.f};
            float cb[4] = {0.f, 0.f, 0.f, 0.f};
            #pragma unroll
            for (int sp = 0; sp < 2; sp++) {
                uint32_t ha[4], hb[4], la[4], lb[4];
                ldsm4(ha[0], ha[1], ha[2], ha[3], aKH + (uint32_t)(ja * 1152 + sp * 64) + lkb);
                ldsm4(hb[0], hb[1], hb[2], hb[3], aKH + (uint32_t)(jb * 1152 + sp * 64) + lkb);
                ldsm4(la[0], la[1], la[2], la[3], aKL + (uint32_t)(ja * 1152 + sp * 64) + lkb);
                ldsm4(lb[0], lb[1], lb[2], lb[3], aKL + (uint32_t)(jb * 1152 + sp * 64) + lkb);
                int s0 = 2 * sp, s1 = 2 * sp + 1;
                mma_bf16(ca, qh[s0], ha);     mma_bf16(cb, qh[s0], hb);
                mma_bf16(ca, qh[s0], la);     mma_bf16(cb, qh[s0], lb);
                mma_bf16(ca, ql[s0], ha);     mma_bf16(cb, ql[s0], hb);
                mma_bf16(ca, qh[s1], ha + 2); mma_bf16(cb, qh[s1], hb + 2);
                mma_bf16(ca, qh[s1], la + 2); mma_bf16(cb, qh[s1], lb + 2);
                mma_bf16(ca, ql[s1], ha + 2); mma_bf16(cb, ql[s1], hb + 2);
            }
            float pa0 = ex2f(fmaf(ca[0], 7.2134752f, -86.5617024f));
            float pa1 = ex2f(fmaf(ca[1], 7.2134752f, -86.5617024f));
            float pa2 = ex2f(fmaf(ca[2], 7.2134752f, -86.5617024f));
            float pa3 = ex2f(fmaf(ca[3], 7.2134752f, -86.5617024f));
            float pb0 = ex2f(fmaf(cb[0], 7.2134752f, -86.5617024f));
            float pb1 = ex2f(fmaf(cb[1], 7.2134752f, -86.5617024f));
            float pb2 = ex2f(fmaf(cb[2], 7.2134752f, -86.5617024f));
            float pb3 = ex2f(fmaf(cb[3], 7.2134752f, -86.5617024f));
            uint32_t a01 = packbf(pa0, pa1), a23 = packbf(pa2, pa3);
            uint32_t b01 = packbf(pb0, pb1), b23 = packbf(pb2, pb3);
            l0 += lo_bf(a01) + hi_bf(a01) + lo_bf(b01) + hi_bf(b01);
            l1 += lo_bf(a23) + hi_bf(a23) + lo_bf(b23) + hi_bf(b23);
            Pp[q0 * 36 + ja * 4 + t4] = a01;
            Pp[(q0 + 8) * 36 + ja * 4 + t4] = a23;
            Pp[q0 * 36 + jb * 4 + t4] = b01;
            Pp[(q0 + 8) * 36 + jb * 4 + t4] = b23;
        }
        __syncwarp();

        #pragma unroll
        for (int s = 0; s < 4; s++) {
            uint32_t a4[4];
            ldsm4(a4[0], a4[1], a4[2], a4[3], aP + (uint32_t)(s * 32) + lpb);
            #pragma unroll
            for (int jp2 = 0; jp2 < 4; jp2++) {
                uint32_t v4[4];
                ldsm4(v4[0], v4[1], v4[2], v4[3],
                      aV + (uint32_t)(jp2 * 2304 + s * 32) + lvb);
                mma_bf16(accO[2 * jp2], a4, v4);
                mma_bf16(accO[2 * jp2 + 1], a4, v4 + 2);
            }
        }
        __syncthreads();
        if (t + 2 < 36) attn_prefetch(sb, st, bb, t + 2);
        CP_COMMIT();
    }

    l0 += __shfl_xor_sync(0xFFFFFFFFu, l0, 1);
    l0 += __shfl_xor_sync(0xFFFFFFFFu, l0, 2);
    l1 += __shfl_xor_sync(0xFFFFFFFFu, l1, 1);
    l1 += __shfl_xor_sync(0xFFFFFFFFu, l1, 2);
    float inv0 = 1.f / l0, inv1 = 1.f / l1;

    float* O0 = g_omap + (size_t)(qbase + q0) * C2_;
    float* O1 = g_omap + (size_t)(qbase + q0 + 8) * C2_;
    #pragma unroll
    for (int j = 0; j < 8; j++) {
        *(float2*)&O0[j * 8 + 2 * t4] = make_float2(accO[j][0] * inv0, accO[j][1] * inv0);
        *(float2*)&O1[j * 8 + 2 * t4] = make_float2(accO[j][2] * inv1, accO[j][3] * inv1);
    }
}

// ---------------- up: one image row per block, coalesced epilogue ----------------
// grid (384, 4): blockIdx.x = b*96 + i (half-res row), blockIdx.y = cb (128 cols).
// 192 threads / 6 warps; warp w covers pixels j in [16w, 16w+16).
#define UP_SMEM 51200
__global__ void __launch_bounds__(192) up_mma_kernel(const float* __restrict__ ub,
                                                     const float* __restrict__ iny,
                                                     const float* __restrict__ gptr,
                                                     float* __restrict__ out) {
    extern __shared__ float sm[];
    uint32_t* BH = (uint32_t*)sm;          // [128][36]
    uint32_t* BL = BH + 4608;
    int tid = threadIdx.x;
    int lane = tid & 31, w = tid >> 5;
    int t4 = lane & 3, t4r = lane >> 2;
    int gi = blockIdx.x;
    int b = gi / 96, i = gi - b * 96;
    int cb = blockIdx.y;

    for (int idx = tid; idx < 4096; idx += 192) {
        int colL = idx >> 5, kp = idx & 31;
        BH[colL * 36 + kp] = g_WcH2[(size_t)(cb * 128 + colL) * 32 + kp];
        BL[colL * 36 + kp] = g_WcL2[(size_t)(cb * 128 + colL) * 32 + kp];
    }
    __syncthreads();

    int jp0 = 16 * w + t4r;                 // pixel j (and +8)
    int r0 = b * NPB + i * ww_ + jp0;
    uint32_t ah[4][4], al[4][4];
    #pragma unroll
    for (int s = 0; s < 4; s++) {
        int col = s * 16 + 2 * t4;
        float2 v00 = *(const float2*)&g_omap[(size_t)r0 * C2_ + col];
        float2 v10 = *(const float2*)&g_omap[(size_t)(r0 + 8) * C2_ + col];
        float2 v01 = *(const float2*)&g_omap[(size_t)r0 * C2_ + col + 8];
        float2 v11 = *(const float2*)&g_omap[(size_t)(r0 + 8) * C2_ + col + 8];
        splitbf(v00.x, v00.y, ah[s][0], al[s][0]);
        splitbf(v10.x, v10.y, ah[s][1], al[s][1]);
        splitbf(v01.x, v01.y, ah[s][2], al[s][2]);
        splitbf(v11.x, v11.y, ah[s][3], al[s][3]);
    }

    float acc[16][4];
    #pragma unroll
    for (int j = 0; j < 16; j++)
        #pragma unroll
        for (int e = 0; e < 4; e++) acc[j][e] = 0.f;

    #pragma unroll
    for (int s = 0; s < 4; s++) {
        #pragma unroll
        for (int j = 0; j < 16; j++) {
            int r = (j * 8 + t4r) * 36 + s * 8 + t4;
            uint32_t bh[2], bl2[2];
            bh[0] = BH[r]; bh[1] = BH[r + 4];
            bl2[0] = BL[r]; bl2[1] = BL[r + 4];
            mma_bf16(acc[j], ah[s], bh);
            mma_bf16(acc[j], ah[s], bl2);
            mma_bf16(acc[j], al[s], bh);
        }
    }
    __syncthreads();                        // done reading BH/BL

    // stage: S[col 128][pix 96+4] floats (overwrites BH/BL space)
    float* S = sm;
    #pragma unroll
    for (int j = 0; j < 16; j++) {
        int colL = j * 8 + 2 * t4;
        S[colL * 100 + jp0]       = acc[j][0];
        S[(colL + 1) * 100 + jp0] = acc[j][1];
        S[colL * 100 + jp0 + 8]       = acc[j][2];
        S[(colL + 1) * 100 + jp0 + 8] = acc[j][3];
    }
    __syncthreads();

    // coalesced write: 64 rows of (oc, pp), each 192 floats
    float gam = *gptr;
    int jj = tid >> 1, q = tid & 1;
    #pragma unroll 4
    for (int r = 0; r < 64; r++) {
        int ocl = r >> 1, pp = r & 1;
        int oc = cb * 32 + ocl;
        float v = S[(ocl * 4 + pp * 2 + q) * 100 + jj];
        size_t o = (((size_t)b * CH_ + oc) * H_ + 2 * i + pp) * W_ + tid;
        out[o] = v + ub[oc] + gam * iny[o];
    }
}

// ---------------- launch ----------------
extern "C" void kernel_launch(void* const* d_in, const int* in_sizes, int n_in,
                              void* d_out, int out_size) {
    const float* input_x = (const float*)d_in[0];
    const float* input_y = (const float*)d_in[1];
    const float* d0w = (const float*)d_in[2];
    const float* d0b = (const float*)d_in[3];
    const float* d1w = (const float*)d_in[4];
    const float* d1b = (const float*)d_in[5];
    const float* thw = (const float*)d_in[6];
    const float* phw = (const float*)d_in[7];
    const float* gw  = (const float*)d_in[8];
    const float* ow  = (const float*)d_in[9];
    const float* uw  = (const float*)d_in[10];
    const float* ub  = (const float*)d_in[11];
    const float* gamma = (const float*)d_in[12];
    float* out = (float*)d_out;

    float *btp, *bg2;
    uint32_t *WtpH2, *WtpL2, *WgH2, *WgL2;
    cudaGetSymbolAddress((void**)&WtpH2, g_WtpH2);
    cudaGetSymbolAddress((void**)&WtpL2, g_WtpL2);
    cudaGetSymbolAddress((void**)&WgH2, g_WgH2);
    cudaGetSymbolAddress((void**)&WgL2, g_WgL2);
    cudaGetSymbolAddress((void**)&btp, g_btp);
    cudaGetSymbolAddress((void**)&bg2, g_bg2);

    const int SM_TP = (4352 + 2 * 16 * 136) * 2 * 4 + 128 * 68 * 4;  // 104448
    const int SM_G  = (4352 + 2 * 16 * 72) * 2 * 4 + 128 * 68 * 4;   // 88064
    cudaFuncSetAttribute(proj_gemm_kernel<128>,
                         cudaFuncAttributeMaxDynamicSharedMemorySize, SM_TP);
    cudaFuncSetAttribute(proj_gemm_kernel<64>,
                         cudaFuncAttributeMaxDynamicSharedMemorySize, SM_G);
    cudaFuncSetAttribute(attn_mma_kernel,
                         cudaFuncAttributeMaxDynamicSharedMemorySize, ATT_SMEM_BYTES);
    cudaFuncSetAttribute(up_mma_kernel,
                         cudaFuncAttributeMaxDynamicSharedMemorySize, UP_SMEM);

    prep_all<<<161, 256>>>(thw, phw, gw, d0w, d1w, d0b, d1b, ow, uw);
    proj_gemm_kernel<128><<<288, 256, SM_TP>>>(input_x, WtpH2, WtpL2, btp);
    proj_gemm_kernel<64><<<288, 256, SM_G>>>(input_y, WgH2, WgL2, bg2);
    attn_mma_kernel<<<288, 256, ATT_SMEM_BYTES>>>();
    up_mma_kernel<<<dim3(384, 4), 192, UP_SMEM>>>(ub, input_y, gamma, out);
}

// round 16
// speedup vs baseline: 1.1491x; 1.1491x over previous
#include <cuda_runtime.h>
#include <cuda_bf16.h>
#include <cstdint>

// ---------------- problem constants ----------------
#define B_    4
#define CH_   128
#define H_    192
#define W_    192
#define ww_   96
#define NPB   9216
#define BN    36864
#define MPB   2304
#define BM    9216
#define C2_   64
#define KD_   512

// attention smem layout (uint32 units)
#define KHO(st) ((st) * 2304)
#define KLO(st) (4608 + (st) * 2304)
#define VO(st)  (9216 + (st) * 2304)
#define PPO     13824
#define ATT_SMEM_BYTES (18432 * 4)   // 73728

// ---------------- device scratch ----------------
__device__ __align__(128) float g_theta[BN * C2_];
__device__ __align__(128) uint32_t g_phiH2[BM * 32];
__device__ __align__(128) uint32_t g_phiL2[BM * 32];
__device__ __align__(128) uint32_t g_gVp[B_ * C2_ * (MPB / 2)];
__device__ __align__(128) float g_omap[BN * C2_];
__device__ __align__(128) uint32_t g_WtpH2[256 * 128];
__device__ __align__(128) uint32_t g_WtpL2[256 * 128];
__device__ __align__(128) uint32_t g_WgH2[256 * 64];
__device__ __align__(128) uint32_t g_WgL2[256 * 64];
__device__ __align__(128) uint32_t g_WcH2[512 * 32];
__device__ __align__(128) uint32_t g_WcL2[512 * 32];
__device__ __align__(128) float g_btp[128];
__device__ __align__(128) float g_bg2[64];

// ---------------- helpers ----------------
__device__ __forceinline__ uint32_t smem_u32(const void* p) {
    uint32_t a;
    asm("{ .reg .u64 t; cvta.to.shared.u64 t, %1; cvt.u32.u64 %0, t; }" : "=r"(a) : "l"(p));
    return a;
}
__device__ __forceinline__ float ex2f(float x) {
    float r; asm("ex2.approx.ftz.f32 %0, %1;" : "=f"(r) : "f"(x)); return r;
}
__device__ __forceinline__ void cpasync16(uint32_t d, const void* s) {
    asm volatile("cp.async.cg.shared.global [%0], [%1], 16;" :: "r"(d), "l"(s));
}
#define CP_COMMIT() asm volatile("cp.async.commit_group;" ::: "memory")
#define CP_WAIT1()  asm volatile("cp.async.wait_group 1;" ::: "memory")
#define CP_WAIT0()  asm volatile("cp.async.wait_group 0;" ::: "memory")

__device__ __forceinline__ void mma_bf16(float* c, const uint32_t* a, const uint32_t* b) {
    asm volatile(
        "mma.sync.aligned.m16n8k16.row.col.f32.bf16.bf16.f32 "
        "{%0,%1,%2,%3},{%4,%5,%6,%7},{%8,%9},{%0,%1,%2,%3};"
        : "+f"(c[0]), "+f"(c[1]), "+f"(c[2]), "+f"(c[3])
        : "r"(a[0]), "r"(a[1]), "r"(a[2]), "r"(a[3]), "r"(b[0]), "r"(b[1]));
}
__device__ __forceinline__ void ldsm4(uint32_t& r0, uint32_t& r1, uint32_t& r2,
                                      uint32_t& r3, uint32_t addr) {
    asm volatile("ldmatrix.sync.aligned.m8n8.x4.shared.b16 {%0,%1,%2,%3}, [%4];"
                 : "=r"(r0), "=r"(r1), "=r"(r2), "=r"(r3) : "r"(addr));
}
__device__ __forceinline__ void splitbf(float x, float y, uint32_t& h, uint32_t& l) {
    __nv_bfloat162 hb = __floats2bfloat162_rn(x, y);
    float hx = __bfloat162float(__low2bfloat16(hb));
    float hy = __bfloat162float(__high2bfloat16(hb));
    __nv_bfloat162 lb = __floats2bfloat162_rn(x - hx, y - hy);
    h = *reinterpret_cast<uint32_t*>(&hb);
    l = *reinterpret_cast<uint32_t*>(&lb);
}
__device__ __forceinline__ uint32_t packbf(float x, float y) {
    __nv_bfloat162 hb = __floats2bfloat162_rn(x, y);
    return *reinterpret_cast<uint32_t*>(&hb);
}
__device__ __forceinline__ float lo_bf(uint32_t u) {
    __nv_bfloat162 v = *reinterpret_cast<__nv_bfloat162*>(&u);
    return __bfloat162float(__low2bfloat16(v));
}
__device__ __forceinline__ float hi_bf(uint32_t u) {
    __nv_bfloat162 v = *reinterpret_cast<__nv_bfloat162*>(&u);
    return __bfloat162float(__high2bfloat16(v));
}

// ---------------- single prep kernel (R12) ----------------
__global__ void __launch_bounds__(256) prep_all(const float* __restrict__ thw,
                                                const float* __restrict__ phw,
                                                const float* __restrict__ gw,
                                                const float* __restrict__ d0w,
                                                const float* __restrict__ d1w,
                                                const float* __restrict__ d0b,
                                                const float* __restrict__ d1b,
                                                const float* __restrict__ ow,
                                                const float* __restrict__ uw) {
    int bid = blockIdx.x, tid = threadIdx.x;
    if (bid < 64) {
        int j = bid * 256 + tid;
        int o = j >> 7, k4 = j & 127;
        const float* wrow = (o < 64) ? (thw + o * CH_) : (phw + (o - 64) * CH_);
        float s0 = 0.f, s1 = 0.f, s2 = 0.f, s3 = 0.f;
        #pragma unroll 4
        for (int c = 0; c < CH_; c++) {
            float w = wrow[c];
            float4 d = *(const float4*)(d0w + (size_t)c * KD_ + 4 * k4);
            s0 += w * d.x; s1 += w * d.y; s2 += w * d.z; s3 += w * d.w;
        }
        uint32_t h, l;
        splitbf(s0, s1, h, l);
        g_WtpH2[(2 * k4) * 128 + o] = h; g_WtpL2[(2 * k4) * 128 + o] = l;
        splitbf(s2, s3, h, l);
        g_WtpH2[(2 * k4 + 1) * 128 + o] = h; g_WtpL2[(2 * k4 + 1) * 128 + o] = l;
    } else if (bid < 96) {
        int j = (bid - 64) * 256 + tid;
        int o = j >> 7, k4 = j & 127;
        float s0 = 0.f, s1 = 0.f, s2 = 0.f, s3 = 0.f;
        #pragma unroll 4
        for (int c = 0; c < CH_; c++) {
            float w = gw[o * CH_ + c];
            float4 d = *(const float4*)(d1w + (size_t)c * KD_ + 4 * k4);
            s0 += w * d.x; s1 += w * d.y; s2 += w * d.z; s3 += w * d.w;
        }
        uint32_t h, l;
        splitbf(s0, s1, h, l);
        g_WgH2[(2 * k4) * 64 + o] = h; g_WgL2[(2 * k4) * 64 + o] = l;
        splitbf(s2, s3, h, l);
        g_WgH2[(2 * k4 + 1) * 64 + o] = h; g_WgL2[(2 * k4 + 1) * 64 + o] = l;
    } else if (bid < 160) {
        int j = (bid - 96) * 256 + tid;
        int col = j >> 5, kp = j & 31;
        float sa = 0.f, sb2 = 0.f;
        #pragma unroll 4
        for (int ic = 0; ic < CH_; ic++) {
            float u = uw[(size_t)ic * 512 + col];
            sa  += ow[ic * C2_ + 2 * kp] * u;
            sb2 += ow[ic * C2_ + 2 * kp + 1] * u;
        }
        uint32_t h, l;
        splitbf(sa, sb2, h, l);
        g_WcH2[col * 32 + kp] = h;
        g_WcL2[col * 32 + kp] = l;
    } else {
        int o = tid;
        if (o < 128) {
            const float* wrow = (o < 64) ? (thw + o * CH_) : (phw + (o - 64) * CH_);
            float s = 0.f;
            for (int c = 0; c < CH_; c++) s += wrow[c] * d0b[c];
            g_btp[o] = s;
        } else if (o < 192) {
            int oo = o - 128;
            float s = 0.f;
            for (int c = 0; c < CH_; c++) s += gw[oo * CH_ + c] * d1b[c];
            g_bg2[oo] = s;
        }
    }
}

// ---------------- fused projection GEMM (R12 verbatim) ----------------
template <int NCOLS>
__global__ void __launch_bounds__(256) proj_gemm_kernel(const float* __restrict__ inp,
                                                        const uint32_t* __restrict__ BH,
                                                        const uint32_t* __restrict__ BL,
                                                        const float* __restrict__ bias) {
    constexpr int BST2 = NCOLS + 8;
    constexpr int SA = 4352;
    constexpr int SB = 16 * BST2;
    constexpr int STAGE = SA + 2 * SB;
    constexpr int NJ = NCOLS / 8;
    constexpr int BOPS = 16 * (NCOLS / 4);
    constexpr int PSTG = 2 * STAGE;

    extern __shared__ float sm[];
    uint32_t sb = smem_u32(sm);
    int tid = threadIdx.x;
    int lane = tid & 31, wm = tid >> 5;
    int t4 = lane & 3, t4r = lane >> 2;

    int blk = blockIdx.x;
    int b = blk / 72, r2 = blk - b * 72;
    int ti = r2 / 3, jt = r2 - ti * 3;
    const float* inb = inp + (size_t)b * CH_ * H_ * W_;

    auto prefetch = [&](int ch, int s) {
        uint32_t offA = sb + (s * STAGE) * 4;
        #pragma unroll
        for (int t = 0; t < 4; t++) {
            int o = tid + t * 256;
            int seg = o >> 4, part = o & 15;
            int ic = seg >> 3, rr = seg & 7;
            const float* src = inb + ((size_t)(ch * 8 + ic) * H_ + 8 * ti + rr) * W_
                               + 64 * jt + part * 4;
            cpasync16(offA + (seg * 68 + part * 4) * 4, src);
        }
        uint32_t offBh = sb + (s * STAGE + SA) * 4;
        uint32_t offBl = sb + (s * STAGE + SA + SB) * 4;
        #pragma unroll
        for (int o = tid; o < BOPS; o += 256) {
            int row = o / (NCOLS / 4), part = o % (NCOLS / 4);
            cpasync16(offBh + (row * BST2 + part * 4) * 4,
                      BH + (size_t)(ch * 16 + row) * NCOLS + part * 4);
            cpasync16(offBl + (row * BST2 + part * 4) * 4,
                      BL + (size_t)(ch * 16 + row) * NCOLS + part * 4);
        }
    };

    prefetch(0, 0); CP_COMMIT();
    prefetch(1, 1); CP_COMMIT();

    float acc[NJ][4];
    #pragma unroll
    for (int j = 0; j < NJ; j++)
        #pragma unroll
        for (int e = 0; e < 4; e++) acc[j][e] = 0.f;

    int n0 = wm * 16 + t4r;
    int rr0 = n0 >> 5, jj = n0 & 31;
    int p = t4 & 1;

    for (int ch = 0; ch < 16; ch++) {
        int st = ch & 1;
        CP_WAIT1();
        __syncthreads();
        const float* As = sm + st * STAGE;
        const uint32_t* Bh = (const uint32_t*)(As + SA);
        const uint32_t* Bl = Bh + SB;

        #pragma unroll
        for (int s = 0; s < 2; s++) {
            int ica = s * 4 + (t4 >> 1);
            const float* Ap = As + (ica * 8 + 2 * rr0 + p) * 68 + 2 * jj;
            float2 x0 = *(const float2*)Ap;
            float2 x1 = *(const float2*)(Ap + 16);
            float2 x2 = *(const float2*)(Ap + 16 * 68);
            float2 x3 = *(const float2*)(Ap + 16 * 68 + 16);
            uint32_t ah[4], al[4];
            splitbf(x0.x, x0.y, ah[0], al[0]);
            splitbf(x1.x, x1.y, ah[1], al[1]);
            splitbf(x2.x, x2.y, ah[2], al[2]);
            splitbf(x3.x, x3.y, ah[3], al[3]);

            int brow = (s * 8 + t4) * BST2 + t4r;
            #pragma unroll
            for (int j = 0; j < NJ; j++) {
                uint32_t bh[2], bl2[2];
                bh[0] = Bh[brow + j * 8];
                bh[1] = Bh[brow + j * 8 + 4 * BST2];
                bl2[0] = Bl[brow + j * 8];
                bl2[1] = Bl[brow + j * 8 + 4 * BST2];
                mma_bf16(acc[j], ah, bh);
                mma_bf16(acc[j], ah, bl2);
                mma_bf16(acc[j], al, bh);
            }
        }
        __syncthreads();
        if (ch + 2 < 16) { prefetch(ch + 2, st); }
        CP_COMMIT();
    }

    float* stg = sm + PSTG;
    int ng0 = b * NPB + (4 * ti + rr0) * ww_ + 32 * jt + jj;

    #pragma unroll
    for (int j = 0; j < NJ; j++) {
        int col = j * 8 + 2 * t4;
        float b0 = bias[col], b1 = bias[col + 1];
        float2 v0 = make_float2(acc[j][0] + b0, acc[j][1] + b1);
        float2 v1 = make_float2(acc[j][2] + b0, acc[j][3] + b1);
        if (NCOLS == 128 && col < 64) {
            *(float2*)&g_theta[(size_t)ng0 * C2_ + col] = v0;
            *(float2*)&g_theta[(size_t)(ng0 + 8) * C2_ + col] = v1;
        } else {
            int c = (NCOLS == 128) ? (col - 64) : col;
            *(float2*)&stg[(rr0 * 32 + jj) * 68 + c] = v0;
            *(float2*)&stg[(rr0 * 32 + jj + 8) * 68 + c] = v1;
        }
    }
    __syncthreads();

    if (NCOLS == 128) {
        #pragma unroll
        for (int t = 0; t < 4; t++) {
            int idx = tid + t * 256;
            int c2 = idx & 31, pj = (idx >> 5) & 15, pr = idx >> 9;
            const float* s00 = stg + ((2 * pr) * 32 + 2 * pj) * 68 + 2 * c2;
            float2 a0 = *(const float2*)s00;
            float2 a1 = *(const float2*)(s00 + 68);
            float2 a2 = *(const float2*)(s00 + 32 * 68);
            float2 a3 = *(const float2*)(s00 + 32 * 68 + 68);
            float vx = fmaxf(fmaxf(a0.x, a1.x), fmaxf(a2.x, a3.x));
            float vy = fmaxf(fmaxf(a0.y, a1.y), fmaxf(a2.y, a3.y));
            uint32_t h, l;
            splitbf(vx, vy, h, l);
            int mm = b * MPB + (2 * ti + pr) * 48 + 16 * jt + pj;
            g_phiH2[(size_t)mm * 32 + c2] = h;
            g_phiL2[(size_t)mm * 32 + c2] = l;
        }
    } else {
        #pragma unroll
        for (int t = 0; t < 4; t++) {
            int idx = tid + t * 256;
            int c = idx & 63, pjp = (idx >> 6) & 7, pr = idx >> 9;
            const float* s00 = stg + ((2 * pr) * 32 + 4 * pjp) * 68 + c;
            float v0 = fmaxf(fmaxf(s00[0], s00[68]),
                             fmaxf(s00[32 * 68], s00[32 * 68 + 68]));
            const float* s01 = s00 + 2 * 68;
            float v1 = fmaxf(fmaxf(s01[0], s01[68]),
                             fmaxf(s01[32 * 68], s01[32 * 68 + 68]));
            int mp = (2 * ti + pr) * 24 + 8 * jt + pjp;
            g_gVp[((size_t)b * C2_ + c) * (MPB / 2) + mp] = packbf(v0, v1);
        }
    }
}

// ---------------- flash attention (R12 verbatim) ----------------
__device__ __forceinline__ void attn_prefetch(uint32_t sb, int s, int b, int t) {
    int tid = threadIdx.x;
    int m0 = t * 64;
    #pragma unroll
    for (int i = 0; i < 2; i++) {
        int id = tid + i * 256;
        int row = id >> 3, seg = id & 7;
        cpasync16(sb + (KHO(s) + row * 36 + seg * 4) * 4,
                  g_phiH2 + (size_t)(b * MPB + m0 + row) * 32 + seg * 4);
        cpasync16(sb + (KLO(s) + row * 36 + seg * 4) * 4,
                  g_phiL2 + (size_t)(b * MPB + m0 + row) * 32 + seg * 4);
        cpasync16(sb + (VO(s) + row * 36 + seg * 4) * 4,
                  g_gVp + ((size_t)b * C2_ + row) * (MPB / 2) + m0 / 2 + seg * 4);
    }
}

__global__ void __launch_bounds__(256) attn_mma_kernel() {
    extern __shared__ float sm[];
    uint32_t sb = smem_u32(sm);
    int tid = threadIdx.x;
    int lane = tid & 31, w = tid >> 5;
    int bb = blockIdx.x / 72, qt = blockIdx.x - bb * 72;
    int qbase = bb * NPB + qt * 128;
    int t4 = lane & 3, t4r = lane >> 2;
    int q0 = 16 * w + t4r;
    int lrow = lane & 7, lg = lane >> 3;

    uint32_t lkb = (lrow * 36 + (lg >> 1) * 8 + (lg & 1) * 4) * 4;
    uint32_t lpb = ((16 * w + (lg & 1) * 8 + lrow) * 36 + (lg >> 1) * 4) * 4;
    uint32_t lvb = (((lg >> 1) * 8 + lrow) * 36 + (lg & 1) * 4) * 4;

    uint32_t qh[4][4], ql[4][4];
    {
        const float* Qg = g_theta + (size_t)qbase * C2_;
        #pragma unroll
        for (int s = 0; s < 4; s++) {
            int col = s * 16 + 2 * t4;
            float2 v00 = *(const float2*)&Qg[(size_t)q0 * C2_ + col];
            float2 v10 = *(const float2*)&Qg[(size_t)(q0 + 8) * C2_ + col];
            float2 v01 = *(const float2*)&Qg[(size_t)q0 * C2_ + col + 8];
            float2 v11 = *(const float2*)&Qg[(size_t)(q0 + 8) * C2_ + col + 8];
            splitbf(v00.x, v00.y, qh[s][0], ql[s][0]);
            splitbf(v10.x, v10.y, qh[s][1], ql[s][1]);
            splitbf(v01.x, v01.y, qh[s][2], ql[s][2]);
            splitbf(v11.x, v11.y, qh[s][3], ql[s][3]);
        }
    }

    attn_prefetch(sb, 0, bb, 0); CP_COMMIT();
    attn_prefetch(sb, 1, bb, 1); CP_COMMIT();

    float accO[8][4];
    #pragma unroll
    for (int j = 0; j < 8; j++)
        #pragma unroll
        for (int e = 0; e < 4; e++) accO[j][e] = 0.f;
    float l0 = 0.f, l1 = 0.f;

    uint32_t* Pp = (uint32_t*)sm + PPO;
    uint32_t aP = sb + PPO * 4;

    for (int t = 0; t < 36; t++) {
        int st = t & 1;
        CP_WAIT1();
        __syncthreads();
        uint32_t aKH = sb + KHO(st) * 4;
        uint32_t aKL = sb + KLO(st) * 4;
        uint32_t aV  = sb + VO(st) * 4;

        #pragma unroll
        for (int jp = 0; jp < 4; jp++) {
            int ja = jp, jb = jp + 4;
            float ca[4] = {0.f, 0.f, 0.f, 0.f};
            float cb[4] = {0.f, 0.f, 0.f, 0.f};
            #pragma unroll
            for (int sp = 0; sp < 2; sp++) {
                uint32_t ha[4], hb[4], la[4], lb[4];
                ldsm4(ha[0], ha[1], ha[2], ha[3], aKH + (uint32_t)(ja * 1152 + sp * 64) + lkb);
                ldsm4(hb[0], hb[1], hb[2], hb[3], aKH + (uint32_t)(jb * 1152 + sp * 64) + lkb);
                ldsm4(la[0], la[1], la[2], la[3], aKL + (uint32_t)(ja * 1152 + sp * 64) + lkb);
                ldsm4(lb[0], lb[1], lb[2], lb[3], aKL + (uint32_t)(jb * 1152 + sp * 64) + lkb);
                int s0 = 2 * sp, s1 = 2 * sp + 1;
                mma_bf16(ca, qh[s0], ha);     mma_bf16(cb, qh[s0], hb);
                mma_bf16(ca, qh[s0], la);     mma_bf16(cb, qh[s0], lb);
                mma_bf16(ca, ql[s0], ha);     mma_bf16(cb, ql[s0], hb);
                mma_bf16(ca, qh[s1], ha + 2); mma_bf16(cb, qh[s1], hb + 2);
                mma_bf16(ca, qh[s1], la + 2); mma_bf16(cb, qh[s1], lb + 2);
                mma_bf16(ca, ql[s1], ha + 2); mma_bf16(cb, ql[s1], hb + 2);
            }
            float pa0 = ex2f(fmaf(ca[0], 7.2134752f, -86.5617024f));
            float pa1 = ex2f(fmaf(ca[1], 7.2134752f, -86.5617024f));
            float pa2 = ex2f(fmaf(ca[2], 7.2134752f, -86.5617024f));
            float pa3 = ex2f(fmaf(ca[3], 7.2134752f, -86.5617024f));
            float pb0 = ex2f(fmaf(cb[0], 7.2134752f, -86.5617024f));
            float pb1 = ex2f(fmaf(cb[1], 7.2134752f, -86.5617024f));
            float pb2 = ex2f(fmaf(cb[2], 7.2134752f, -86.5617024f));
            float pb3 = ex2f(fmaf(cb[3], 7.2134752f, -86.5617024f));
            uint32_t a01 = packbf(pa0, pa1), a23 = packbf(pa2, pa3);
            uint32_t b01 = packbf(pb0, pb1), b23 = packbf(pb2, pb3);
            l0 += lo_bf(a01) + hi_bf(a01) + lo_bf(b01) + hi_bf(b01);
            l1 += lo_bf(a23) + hi_bf(a23) + lo_bf(b23) + hi_bf(b23);
            Pp[q0 * 36 + ja * 4 + t4] = a01;
            Pp[(q0 + 8) * 36 + ja * 4 + t4] = a23;
            Pp[q0 * 36 + jb * 4 + t4] = b01;
            Pp[(q0 + 8) * 36 + jb * 4 + t4] = b23;
        }
        __syncwarp();

        #pragma unroll
        for (int s = 0; s < 4; s++) {
            uint32_t a4[4];
            ldsm4(a4[0], a4[1], a4[2], a4[3], aP + (uint32_t)(s * 32) + lpb);
            #pragma unroll
            for (int jp2 = 0; jp2 < 4; jp2++) {
                uint32_t v4[4];
                ldsm4(v4[0], v4[1], v4[2], v4[3],
                      aV + (uint32_t)(jp2 * 2304 + s * 32) + lvb);
                mma_bf16(accO[2 * jp2], a4, v4);
                mma_bf16(accO[2 * jp2 + 1], a4, v4 + 2);
            }
        }
        __syncthreads();
        if (t + 2 < 36) attn_prefetch(sb, st, bb, t + 2);
        CP_COMMIT();
    }

    l0 += __shfl_xor_sync(0xFFFFFFFFu, l0, 1);
    l0 += __shfl_xor_sync(0xFFFFFFFFu, l0, 2);
    l1 += __shfl_xor_sync(0xFFFFFFFFu, l1, 1);
    l1 += __shfl_xor_sync(0xFFFFFFFFu, l1, 2);
    float inv0 = 1.f / l0, inv1 = 1.f / l1;

    float* O0 = g_omap + (size_t)(qbase + q0) * C2_;
    float* O1 = g_omap + (size_t)(qbase + q0 + 8) * C2_;
    #pragma unroll
    for (int j = 0; j < 8; j++) {
        *(float2*)&O0[j * 8 + 2 * t4] = make_float2(accO[j][0] * inv0, accO[j][1] * inv0);
        *(float2*)&O1[j * 8 + 2 * t4] = make_float2(accO[j][2] * inv1, accO[j][3] * inv1);
    }
}

// ---------------- up: coalesced, cp.async weights, batched epilogue ----------------
#define UP_SMEM 51328
__global__ void __launch_bounds__(192) up_mma_kernel(const float* __restrict__ ub,
                                                     const float* __restrict__ iny,
                                                     const float* __restrict__ gptr,
                                                     float* __restrict__ out) {
    extern __shared__ float sm[];
    uint32_t sb = smem_u32(sm);
    uint32_t* BH = (uint32_t*)sm;          // [128][36]
    uint32_t* BL = BH + 4608;
    float* ubs = sm + 12800;               // 32 floats, above the S region
    int tid = threadIdx.x;
    int lane = tid & 31, w = tid >> 5;
    int t4 = lane & 3, t4r = lane >> 2;
    int gi = blockIdx.x;
    int b = gi / 96, i = gi - b * 96;
    int cb = blockIdx.y;

    // weights via cp.async (fire-and-forget; ragged loop is harmless)
    for (int idx = tid; idx < 2048; idx += 192) {
        int m = idx >> 10;
        int r = idx & 1023;
        int colL = r >> 3, seg = r & 7;
        const uint32_t* src = (m ? g_WcL2 : g_WcH2)
                              + (size_t)(cb * 128 + colL) * 32 + seg * 4;
        cpasync16(sb + (m * 4608 + colL * 36 + seg * 4) * 4, src);
    }
    if (tid < 32) ubs[tid] = ub[cb * 32 + tid];
    CP_COMMIT();
    CP_WAIT0();
    __syncthreads();

    int jp0 = 16 * w + t4r;                 // pixel j (and +8)
    int r0 = b * NPB + i * ww_ + jp0;
    uint32_t ah[4][4], al[4][4];
    #pragma unroll
    for (int s = 0; s < 4; s++) {
        int col = s * 16 + 2 * t4;
        float2 v00 = *(const float2*)&g_omap[(size_t)r0 * C2_ + col];
        float2 v10 = *(const float2*)&g_omap[(size_t)(r0 + 8) * C2_ + col];
        float2 v01 = *(const float2*)&g_omap[(size_t)r0 * C2_ + col + 8];
        float2 v11 = *(const float2*)&g_omap[(size_t)(r0 + 8) * C2_ + col + 8];
        splitbf(v00.x, v00.y, ah[s][0], al[s][0]);
        splitbf(v10.x, v10.y, ah[s][1], al[s][1]);
        splitbf(v01.x, v01.y, ah[s][2], al[s][2]);
        splitbf(v11.x, v11.y, ah[s][3], al[s][3]);
    }

    float acc[16][4];
    #pragma unroll
    for (int j = 0; j < 16; j++)
        #pragma unroll
        for (int e = 0; e < 4; e++) acc[j][e] = 0.f;

    #pragma unroll
    for (int s = 0; s < 4; s++) {
        #pragma unroll
        for (int j = 0; j < 16; j++) {
            int r = (j * 8 + t4r) * 36 + s * 8 + t4;
            uint32_t bh[2], bl2[2];
            bh[0] = BH[r]; bh[1] = BH[r + 4];
            bl2[0] = BL[r]; bl2[1] = BL[r + 4];
            mma_bf16(acc[j], ah[s], bh);
            mma_bf16(acc[j], ah[s], bl2);
            mma_bf16(acc[j], al[s], bh);
        }
    }
    __syncthreads();                        // done reading BH/BL

    // stage: S[col 128][pix 100]
    float* S = sm;
    #pragma unroll
    for (int j = 0; j < 16; j++) {
        int colL = j * 8 + 2 * t4;
        S[colL * 100 + jp0]           = acc[j][0];
        S[(colL + 1) * 100 + jp0]     = acc[j][1];
        S[colL * 100 + jp0 + 8]       = acc[j][2];
        S[(colL + 1) * 100 + jp0 + 8] = acc[j][3];
    }
    __syncthreads();

    // coalesced writes, batched x8 for MLP
    float gam = *gptr;
    int jj = tid >> 1, q = tid & 1;
    size_t rowbase = (((size_t)b * CH_ + cb * 32) * H_ + 2 * i) * W_ + tid;
    #pragma unroll
    for (int rb = 0; rb < 64; rb += 8) {
        float yv[8], sv[8], uv[8];
        size_t ofs[8];
        #pragma unroll
        for (int k = 0; k < 8; k++) {
            int r = rb + k;
            int ocl = r >> 1, pp = r & 1;
            ofs[k] = rowbase + (size_t)ocl * (H_ * W_) + (size_t)pp * W_;
            yv[k] = iny[ofs[k]];
            sv[k] = S[(ocl * 4 + pp * 2 + q) * 100 + jj];
            uv[k] = ubs[ocl];
        }
        #pragma unroll
        for (int k = 0; k < 8; k++)
            out[ofs[k]] = sv[k] + uv[k] + gam * yv[k];
    }
}

// ---------------- launch ----------------
extern "C" void kernel_launch(void* const* d_in, const int* in_sizes, int n_in,
                              void* d_out, int out_size) {
    const float* input_x = (const float*)d_in[0];
    const float* input_y = (const float*)d_in[1];
    const float* d0w = (const float*)d_in[2];
    const float* d0b = (const float*)d_in[3];
    const float* d1w = (const float*)d_in[4];
    const float* d1b = (const float*)d_in[5];
    const float* thw = (const float*)d_in[6];
    const float* phw = (const float*)d_in[7];
    const float* gw  = (const float*)d_in[8];
    const float* ow  = (const float*)d_in[9];
    const float* uw  = (const float*)d_in[10];
    const float* ub  = (const float*)d_in[11];
    const float* gamma = (const float*)d_in[12];
    float* out = (float*)d_out;

    float *btp, *bg2;
    uint32_t *WtpH2, *WtpL2, *WgH2, *WgL2;
    cudaGetSymbolAddress((void**)&WtpH2, g_WtpH2);
    cudaGetSymbolAddress((void**)&WtpL2, g_WtpL2);
    cudaGetSymbolAddress((void**)&WgH2, g_WgH2);
    cudaGetSymbolAddress((void**)&WgL2, g_WgL2);
    cudaGetSymbolAddress((void**)&btp, g_btp);
    cudaGetSymbolAddress((void**)&bg2, g_bg2);

    const int SM_TP = (4352 + 2 * 16 * 136) * 2 * 4 + 128 * 68 * 4;  // 104448
    const int SM_G  = (4352 + 2 * 16 * 72) * 2 * 4 + 128 * 68 * 4;   // 88064
    cudaFuncSetAttribute(proj_gemm_kernel<128>,
                         cudaFuncAttributeMaxDynamicSharedMemorySize, SM_TP);
    cudaFuncSetAttribute(proj_gemm_kernel<64>,
                         cudaFuncAttributeMaxDynamicSharedMemorySize, SM_G);
    cudaFuncSetAttribute(attn_mma_kernel,
                         cudaFuncAttributeMaxDynamicSharedMemorySize, ATT_SMEM_BYTES);
    cudaFuncSetAttribute(up_mma_kernel,
                         cudaFuncAttributeMaxDynamicSharedMemorySize, UP_SMEM);

    prep_all<<<161, 256>>>(thw, phw, gw, d0w, d1w, d0b, d1b, ow, uw);
    proj_gemm_kernel<128><<<288, 256, SM_TP>>>(input_x, WtpH2, WtpL2, btp);
    proj_gemm_kernel<64><<<288, 256, SM_G>>>(input_y, WgH2, WgL2, bg2);
    attn_mma_kernel<<<288, 256, ATT_SMEM_BYTES>>>();
    up_mma_kernel<<<dim3(384, 4), 192, UP_SMEM>>>(ub, input_y, gamma, out);
}